// round 1
// baseline (speedup 1.0000x reference)
#include <cuda_runtime.h>
#include <cuda_bf16.h>

// Problem constants (fixed shapes per reference)
#define NB  500000   // batch
#define D   300      // term dim
#define KP  320      // padded k (term dim) for lane slicing
#define NR  40       // relations
#define RD  5        // relation dim
#define TS  32       // samples per energy tile
#define JP  8        // M rows per smem panel
#define NHB 128      // histogram/scatter blocks
#define CH  ((NB + NHB - 1) / NHB)   // samples per hist block
#define MAX_TILES 512                 // >= ceil(max bucket / TS); bucket ~12.5K << 16384

// Device scratch (allocation-free rule: __device__ globals)
__device__ float g_M[(size_t)NR * D * KP];   // per-relation combined matrix, k-padded, 15.4MB
__device__ int   g_order[NB];                // sample ids grouped by relation
__device__ int   g_offsets[NR + 1];          // bucket offsets
__device__ int   g_blkhist[NHB * NR];
__device__ int   g_blkbase[NHB * NR];

// ---------------------------------------------------------------------------
// Kernel 1: M[r][j][k] = sum_i rel_table[r][i] * assoc[i][j][k]   (k>=300 -> 0)
// grid (NR, 30): each block does 10 j-rows for one relation
// ---------------------------------------------------------------------------
__global__ void k_buildM(const float* __restrict__ rel_table,
                         const float* __restrict__ assoc) {
    int r = blockIdx.x;
    int chunk = blockIdx.y;  // 30 chunks of 10 rows each
    float rv[RD];
#pragma unroll
    for (int i = 0; i < RD; i++) rv[i] = rel_table[r * RD + i];
    for (int idx = threadIdx.x; idx < 10 * KP; idx += blockDim.x) {
        int j = chunk * 10 + idx / KP;
        int k = idx % KP;
        float v = 0.f;
        if (k < D) {
#pragma unroll
            for (int i = 0; i < RD; i++)
                v += rv[i] * assoc[((size_t)i * D + j) * D + k];
        }
        g_M[((size_t)r * D + j) * KP + k] = v;
    }
}

// ---------------------------------------------------------------------------
// Kernel 2: per-block histogram of relations
// ---------------------------------------------------------------------------
__global__ void k_hist(const int* __restrict__ rels) {
    __shared__ int h[NR];
    if (threadIdx.x < NR) h[threadIdx.x] = 0;
    __syncthreads();
    int start = blockIdx.x * CH;
    int end = min(NB, start + CH);
    for (int i = start + threadIdx.x; i < end; i += blockDim.x)
        atomicAdd(&h[rels[i]], 1);
    __syncthreads();
    if (threadIdx.x < NR) g_blkhist[blockIdx.x * NR + threadIdx.x] = h[threadIdx.x];
}

// ---------------------------------------------------------------------------
// Kernel 3: scan -> global bucket offsets + per-(block,rel) scatter bases
// single block, 64 threads
// ---------------------------------------------------------------------------
__global__ void k_scan() {
    __shared__ int tot[NR];
    int r = threadIdx.x;
    if (r < NR) {
        int run = 0;
        for (int b = 0; b < NHB; b++) {
            int v = g_blkhist[b * NR + r];
            g_blkbase[b * NR + r] = run;   // prefix within relation across blocks
            run += v;
        }
        tot[r] = run;
    }
    __syncthreads();
    if (threadIdx.x == 0) {
        int acc = 0;
        for (int rr = 0; rr < NR; rr++) { g_offsets[rr] = acc; acc += tot[rr]; }
        g_offsets[NR] = acc;
    }
    __syncthreads();
    if (r < NR) {
        int off = g_offsets[r];
        for (int b = 0; b < NHB; b++) g_blkbase[b * NR + r] += off;
    }
}

// ---------------------------------------------------------------------------
// Kernel 4: scatter sample ids into relation buckets
// ---------------------------------------------------------------------------
__global__ void k_scatter(const int* __restrict__ rels) {
    __shared__ int cur[NR];
    if (threadIdx.x < NR) cur[threadIdx.x] = g_blkbase[blockIdx.x * NR + threadIdx.x];
    __syncthreads();
    int start = blockIdx.x * CH;
    int end = min(NB, start + CH);
    for (int i = start + threadIdx.x; i < end; i += blockDim.x) {
        int pos = atomicAdd(&cur[rels[i]], 1);
        g_order[pos] = i;
    }
}

// ---------------------------------------------------------------------------
// Kernel 5: energy. Block = (tile of TS=32 samples, one relation).
// Each warp owns 4 samples. Each lane owns a 10-float k-slice
// (k = 4*lane..4*lane+3, 128+4*lane.., 256+2*lane..) of the padded 320 dim.
// w[s][k] = sum_j tL[s][j] * M[j][k] accumulated in registers over j-panels
// staged in smem; epilogue dots w with tR and warp-reduces.
// ---------------------------------------------------------------------------
extern __shared__ float smem_dyn[];

__global__ __launch_bounds__(256, 2)
void k_energy(const int* __restrict__ terms_L,
              const int* __restrict__ terms_R,
              const float* __restrict__ term_table,
              float* __restrict__ out) {
    int r = blockIdx.y;
    int tile = blockIdx.x;
    int bucket_lo = g_offsets[r];
    int cnt = g_offsets[r + 1] - bucket_lo;
    if (tile * TS >= cnt) return;
    int base = bucket_lo + tile * TS;
    int n = min(TS, cnt - tile * TS);

    float* sTR = smem_dyn;               // [TS][KP]
    float* sTL = sTR + TS * KP;          // [TS][D]
    float* sM  = sTL + TS * D;           // [JP][KP]
    int* sSid  = (int*)(sM + JP * KP);   // [TS]
    int* sIL   = sSid + TS;              // [TS]
    int* sIR   = sIL + TS;               // [TS]

    int tid = threadIdx.x;
    if (tid < TS) {
        int sid = (tid < n) ? g_order[base + tid] : -1;
        sSid[tid] = sid;
        sIL[tid] = (sid >= 0) ? terms_L[sid] : 0;
        sIR[tid] = (sid >= 0) ? terms_R[sid] : 0;
    }
    __syncthreads();

    // gather tL / tR rows (coalesced, zero-pad k >= D for tR)
    for (int s = 0; s < TS; s++) {
        const float* rowR = term_table + (size_t)sIR[s] * D;
        const float* rowL = term_table + (size_t)sIL[s] * D;
        for (int k = tid; k < KP; k += 256)
            sTR[s * KP + k] = (k < D) ? rowR[k] : 0.f;
        for (int k = tid; k < D; k += 256)
            sTL[s * D + k] = rowL[k];
    }

    int lane = tid & 31;
    int w = tid >> 5;   // warp id -> samples 4w..4w+3

    float wacc[4][10];
#pragma unroll
    for (int a = 0; a < 4; a++)
#pragma unroll
        for (int q = 0; q < 10; q++) wacc[a][q] = 0.f;

    const float* Mr = g_M + (size_t)r * D * KP;

    for (int j0 = 0; j0 < D; j0 += JP) {
        __syncthreads();
        int jmax = min(JP, D - j0);
        for (int i = tid; i < jmax * KP; i += 256) {
            int jj = i / KP, k = i % KP;
            sM[jj * KP + k] = Mr[(size_t)(j0 + jj) * KP + k];
        }
        __syncthreads();
        for (int jj = 0; jj < jmax; jj++) {
            float4 mA = *(const float4*)&sM[jj * KP + 4 * lane];
            float4 mB = *(const float4*)&sM[jj * KP + 128 + 4 * lane];
            float2 mC = *(const float2*)&sM[jj * KP + 256 + 2 * lane];
#pragma unroll
            for (int ss = 0; ss < 4; ss++) {
                float a = sTL[(4 * w + ss) * D + j0 + jj];  // broadcast within warp
                wacc[ss][0] += a * mA.x;
                wacc[ss][1] += a * mA.y;
                wacc[ss][2] += a * mA.z;
                wacc[ss][3] += a * mA.w;
                wacc[ss][4] += a * mB.x;
                wacc[ss][5] += a * mB.y;
                wacc[ss][6] += a * mB.z;
                wacc[ss][7] += a * mB.w;
                wacc[ss][8] += a * mC.x;
                wacc[ss][9] += a * mC.y;
            }
        }
    }

    // epilogue: e[s] = sum_k w[s][k] * tR[s][k], warp-reduce over lanes
#pragma unroll
    for (int ss = 0; ss < 4; ss++) {
        int s = 4 * w + ss;
        float4 rA = *(const float4*)&sTR[s * KP + 4 * lane];
        float4 rB = *(const float4*)&sTR[s * KP + 128 + 4 * lane];
        float2 rC = *(const float2*)&sTR[s * KP + 256 + 2 * lane];
        float e = wacc[ss][0] * rA.x + wacc[ss][1] * rA.y
                + wacc[ss][2] * rA.z + wacc[ss][3] * rA.w
                + wacc[ss][4] * rB.x + wacc[ss][5] * rB.y
                + wacc[ss][6] * rB.z + wacc[ss][7] * rB.w
                + wacc[ss][8] * rC.x + wacc[ss][9] * rC.y;
#pragma unroll
        for (int off = 16; off > 0; off >>= 1)
            e += __shfl_xor_sync(0xffffffffu, e, off);
        if (lane == 0) {
            int sid = sSid[s];
            if (sid >= 0) out[sid] = e;
        }
    }
}

// ---------------------------------------------------------------------------
// launch
// ---------------------------------------------------------------------------
static const int SMEM_ENERGY = (TS * KP + TS * D + JP * KP) * 4 + 3 * TS * 4; // ~90KB

extern "C" void kernel_launch(void* const* d_in, const int* in_sizes, int n_in,
                              void* d_out, int out_size) {
    const int*   rels       = (const int*)d_in[0];
    const int*   terms_L    = (const int*)d_in[1];
    const int*   terms_R    = (const int*)d_in[2];
    const float* term_table = (const float*)d_in[3];
    const float* rel_table  = (const float*)d_in[4];
    const float* assoc      = (const float*)d_in[5];
    float*       out        = (float*)d_out;

    // >48KB dynamic smem opt-in (host-side attribute; idempotent, not a graph op)
    cudaFuncSetAttribute(k_energy, cudaFuncAttributeMaxDynamicSharedMemorySize,
                         SMEM_ENERGY);

    k_buildM<<<dim3(NR, 30), 256>>>(rel_table, assoc);
    k_hist<<<NHB, 256>>>(rels);
    k_scan<<<1, 64>>>();
    k_scatter<<<NHB, 256>>>(rels);
    k_energy<<<dim3(MAX_TILES, NR), 256, SMEM_ENERGY>>>(terms_L, terms_R,
                                                        term_table, out);
}

// round 4
// speedup vs baseline: 2.8166x; 2.8166x over previous
#include <cuda_runtime.h>
#include <cuda_fp16.h>
#include <cstdint>

// ---------------------------------------------------------------------------
// Problem constants
// ---------------------------------------------------------------------------
#define NB  500000
#define D   300
#define NR  40
#define RD  5
#define NHB 128
#define CH  ((NB + NHB - 1) / NHB)
#define TILE_M    128
#define MAX_TILES 128          // buckets ~12.5K +- ~400 << 16384
#define STRIDE_A  648          // fp16 elems per A row (640 data + 8 pad)
#define STRIDE_B  72           // fp16 elems per B chunk row (64 data + 8 pad)
#define A_BYTES   (TILE_M * STRIDE_A * 2)      // 165888
#define BBUF_BYTES (64 * STRIDE_B * 2)         // 9216
#define NSTAGES   75           // 5 n-chunks x 3 passes x 5 k-chunks

// ---------------------------------------------------------------------------
// Device scratch
// ---------------------------------------------------------------------------
__device__ __half g_Bhi[(size_t)NR * 320 * 320];   // [r][n][k(j)] row-major
__device__ __half g_Blo[(size_t)NR * 320 * 320];
__device__ int g_order[NB];
__device__ int g_offsets[NR + 1];
__device__ int g_blkhist[NHB * NR];
__device__ int g_blkbase[NHB * NR];

// ---------------------------------------------------------------------------
// sm_80-era primitives (compile-safe on plain sm_103: no tcgen05 anywhere)
// ---------------------------------------------------------------------------
__device__ __forceinline__ uint32_t smem_u32(const void* p) {
    uint32_t a;
    asm("{ .reg .u64 t; cvta.to.shared.u64 t, %1; cvt.u32.u64 %0, t; }"
        : "=r"(a) : "l"(p));
    return a;
}
__device__ __forceinline__ void ldsm_x4(uint32_t r[4], uint32_t addr) {
    asm volatile("ldmatrix.sync.aligned.m8n8.x4.shared.b16 {%0,%1,%2,%3}, [%4];"
                 : "=r"(r[0]), "=r"(r[1]), "=r"(r[2]), "=r"(r[3]) : "r"(addr));
}
__device__ __forceinline__ void mma16816(float c[4], const uint32_t a[4],
                                         const uint32_t b0, const uint32_t b1) {
    asm volatile(
        "mma.sync.aligned.m16n8k16.row.col.f32.f16.f16.f32 "
        "{%0,%1,%2,%3}, {%4,%5,%6,%7}, {%8,%9}, {%0,%1,%2,%3};"
        : "+f"(c[0]), "+f"(c[1]), "+f"(c[2]), "+f"(c[3])
        : "r"(a[0]), "r"(a[1]), "r"(a[2]), "r"(a[3]), "r"(b0), "r"(b1));
}
__device__ __forceinline__ void cp_async16(uint32_t dst, const void* src) {
    asm volatile("cp.async.cg.shared.global [%0], [%1], 16;" :: "r"(dst), "l"(src));
}
#define CP_COMMIT() asm volatile("cp.async.commit_group;" ::: "memory")
#define CP_WAIT0()  asm volatile("cp.async.wait_group 0;" ::: "memory")

// ---------------------------------------------------------------------------
// Kernel 1: B tables. B[r][n][k=j] = sum_i rel[r,i]*assoc[i][j][n], fp16 hi/lo,
// zero-padded to 320x320. Transpose through smem for coalesced in/out.
// grid (NR, 25): 64j x 64n tile per block.
// ---------------------------------------------------------------------------
__global__ void k_buildB(const float* __restrict__ rel_table,
                         const float* __restrict__ assoc) {
    __shared__ float sm[64][65];
    int r = blockIdx.x, jc = blockIdx.y / 5, nc = blockIdx.y % 5;
    float rv[RD];
#pragma unroll
    for (int i = 0; i < RD; ++i) rv[i] = rel_table[r * RD + i];
#pragma unroll
    for (int it = 0; it < 16; ++it) {
        int idx = threadIdx.x + it * 256;
        int jl = idx >> 6, nl = idx & 63;
        int j = jc * 64 + jl, n = nc * 64 + nl;
        float v = 0.f;
        if (j < D && n < D) {
#pragma unroll
            for (int i = 0; i < RD; ++i)
                v += rv[i] * assoc[((size_t)i * D + j) * D + n];
        }
        sm[jl][nl] = v;
    }
    __syncthreads();
#pragma unroll
    for (int it = 0; it < 16; ++it) {
        int idx = threadIdx.x + it * 256;
        int nl = idx >> 6, jl = idx & 63;
        float v = sm[jl][nl];
        __half hi = __float2half_rn(v);
        __half lo = __float2half_rn(v - __half2float(hi));
        size_t o = ((size_t)r * 320 + nc * 64 + nl) * 320 + jc * 64 + jl;
        g_Bhi[o] = hi;
        g_Blo[o] = lo;
    }
}

// ---------------------------------------------------------------------------
// Kernels 2-4: counting sort by relation (verified in R1)
// ---------------------------------------------------------------------------
__global__ void k_hist(const int* __restrict__ rels) {
    __shared__ int h[NR];
    if (threadIdx.x < NR) h[threadIdx.x] = 0;
    __syncthreads();
    int start = blockIdx.x * CH, end = min(NB, start + CH);
    for (int i = start + threadIdx.x; i < end; i += blockDim.x)
        atomicAdd(&h[rels[i]], 1);
    __syncthreads();
    if (threadIdx.x < NR) g_blkhist[blockIdx.x * NR + threadIdx.x] = h[threadIdx.x];
}

__global__ void k_scan() {
    __shared__ int tot[NR];
    int r = threadIdx.x;
    if (r < NR) {
        int run = 0;
        for (int b = 0; b < NHB; b++) {
            g_blkbase[b * NR + r] = run;
            run += g_blkhist[b * NR + r];
        }
        tot[r] = run;
    }
    __syncthreads();
    if (threadIdx.x == 0) {
        int acc = 0;
        for (int rr = 0; rr < NR; rr++) { g_offsets[rr] = acc; acc += tot[rr]; }
        g_offsets[NR] = acc;
    }
    __syncthreads();
    if (r < NR) {
        int off = g_offsets[r];
        for (int b = 0; b < NHB; b++) g_blkbase[b * NR + r] += off;
    }
}

__global__ void k_scatter(const int* __restrict__ rels) {
    __shared__ int cur[NR];
    if (threadIdx.x < NR) cur[threadIdx.x] = g_blkbase[blockIdx.x * NR + threadIdx.x];
    __syncthreads();
    int start = blockIdx.x * CH, end = min(NB, start + CH);
    for (int i = start + threadIdx.x; i < end; i += blockDim.x) {
        int pos = atomicAdd(&cur[rels[i]], 1);
        g_order[pos] = i;
    }
}

// ---------------------------------------------------------------------------
// Kernel 5: HMMA energy. Block = 128 samples of one relation, 8 warps (4m x 2n).
//   A smem [128][648] fp16: cols 0..319 = tL hi, 320..639 = tL lo
//   B streamed via cp.async double buffer, [64n x 64k] chunks
//   75 stages: nc(5) x pass(3: hi.hi, lo.hi, hi.lo) x kc(5)
//   epilogue per n-chunk: dot W fragments with tR straight from gmem
//   FINAL: cross-warp (wn=0 + wn=1) reduction through smem  <-- R3 bug fix
// ---------------------------------------------------------------------------
#define SMEM_REQ (A_BYTES + 2 * BBUF_BYTES + 1536 + 768)

extern __shared__ char smem_dyn[];

__global__ __launch_bounds__(256, 1)
void k_energy(const int* __restrict__ terms_L,
              const int* __restrict__ terms_R,
              const float* __restrict__ term_table,
              float* __restrict__ out) {
    int r = blockIdx.y;
    int tile = blockIdx.x;
    int lo_off = g_offsets[r];
    int cnt = g_offsets[r + 1] - lo_off;
    if (tile * TILE_M >= cnt) return;
    int base = lo_off + tile * TILE_M;
    int nvalid = min(TILE_M, cnt - tile * TILE_M);

    char* sA = smem_dyn;
    char* sB = smem_dyn + A_BYTES;
    int* sSid = (int*)(smem_dyn + A_BYTES + 2 * BBUF_BYTES);
    int* sIL = sSid + TILE_M;
    int* sIR = sIL + TILE_M;
    float* sE = (float*)(sIR + TILE_M);      // [128] cross-warp energy partials
    uint32_t u_sA = smem_u32(sA);
    uint32_t u_sB = smem_u32(sB);

    int tid = threadIdx.x;
    int lane = tid & 31;
    int wid = tid >> 5;
    int wm = wid & 3;      // m-warp: rows wm*32..wm*32+31
    int wn = wid >> 2;     // n-warp: cols wn*32..wn*32+31 (within 64-chunk)

    if (tid < TILE_M) {
        int sid = (tid < nvalid) ? g_order[base + tid] : -1;
        sSid[tid] = sid;
        sIL[tid] = (sid >= 0) ? terms_L[sid] : 0;
        sIR[tid] = (sid >= 0) ? terms_R[sid] : 0;
    }
    __syncthreads();

    // Build A: fp16 hi (cols 0..319) and lo (cols 320..639), zero-pad k>=300
#pragma unroll 4
    for (int idx = tid; idx < TILE_M * 160; idx += 256) {
        int m = idx / 160;
        int c2 = (idx % 160) * 2;
        float2 v = make_float2(0.f, 0.f);
        if (c2 < D)
            v = *reinterpret_cast<const float2*>(term_table + (size_t)sIL[m] * D + c2);
        __half hx = __float2half_rn(v.x), hy = __float2half_rn(v.y);
        __half lx = __float2half_rn(v.x - __half2float(hx));
        __half ly = __float2half_rn(v.y - __half2float(hy));
        __half2 hh = __halves2half2(hx, hy);
        __half2 ll = __halves2half2(lx, ly);
        *reinterpret_cast<__half2*>(sA + ((size_t)m * STRIDE_A + c2) * 2) = hh;
        *reinterpret_cast<__half2*>(sA + ((size_t)m * STRIDE_A + 320 + c2) * 2) = ll;
    }

    // Stage B chunk for stage index s into buffer (s&1)
    auto stage = [&](int s) {
        int nc = s / 15, sub = s % 15, ps = sub / 5, kc = sub % 5;
        const __half* tbl = (ps == 2) ? g_Blo : g_Bhi;
        const __half* srcbase = tbl + ((size_t)r * 320 + nc * 64) * 320 + kc * 64;
        uint32_t dstbase = u_sB + (uint32_t)(s & 1) * BBUF_BYTES;
#pragma unroll
        for (int i = 0; i < 2; ++i) {
            int t = tid + i * 256;
            int row = t >> 3, seg = t & 7;
            cp_async16(dstbase + row * (STRIDE_B * 2) + seg * 16,
                       (const char*)(srcbase + (size_t)row * 320) + seg * 16);
        }
        CP_COMMIT();
    };

    stage(0);

    float c[2][4][4];
    float e[4] = {0.f, 0.f, 0.f, 0.f};

    for (int s = 0; s < NSTAGES; ++s) {
        CP_WAIT0();
        __syncthreads();
        if (s + 1 < NSTAGES) stage(s + 1);

        int nc = s / 15, sub = s % 15, ps = sub / 5, kc = sub % 5;
        if (sub == 0) {
#pragma unroll
            for (int mi = 0; mi < 2; ++mi)
#pragma unroll
                for (int ni = 0; ni < 4; ++ni)
#pragma unroll
                    for (int q = 0; q < 4; ++q) c[mi][ni][q] = 0.f;
        }
        int abase = ((ps == 1) ? 320 : 0) + kc * 64;
        uint32_t bbuf = u_sB + (uint32_t)(s & 1) * BBUF_BYTES;

#pragma unroll
        for (int k16 = 0; k16 < 4; ++k16) {
            uint32_t a[2][4];
#pragma unroll
            for (int mi = 0; mi < 2; ++mi) {
                int arow = wm * 32 + mi * 16 + (lane & 15);
                int acol = abase + k16 * 16 + (lane >> 4) * 8;
                ldsm_x4(a[mi], u_sA + (arow * STRIDE_A + acol) * 2);
            }
            uint32_t b[2][4];
#pragma unroll
            for (int g = 0; g < 2; ++g) {
                int brow = wn * 32 + g * 16 + ((lane >> 4) << 3) + (lane & 7);
                int bcol = k16 * 16 + ((lane >> 3) & 1) * 8;
                ldsm_x4(b[g], bbuf + (brow * STRIDE_B + bcol) * 2);
            }
#pragma unroll
            for (int mi = 0; mi < 2; ++mi)
#pragma unroll
                for (int ni = 0; ni < 4; ++ni)
                    mma16816(c[mi][ni], a[mi], b[ni >> 1][(ni & 1) * 2],
                             b[ni >> 1][(ni & 1) * 2 + 1]);
        }

        if (sub == 14) {
            // epilogue for n-chunk nc: e += W (.) tR
#pragma unroll
            for (int mi = 0; mi < 2; ++mi) {
                int row0 = wm * 32 + mi * 16 + (lane >> 2);
                int row1 = row0 + 8;
                const float* p0 = term_table + (size_t)sIR[row0] * D;
                const float* p1 = term_table + (size_t)sIR[row1] * D;
#pragma unroll
                for (int ni = 0; ni < 4; ++ni) {
                    int col = nc * 64 + wn * 32 + ni * 8 + 2 * (lane & 3);
                    if (col < D) {
                        float2 t0 = *reinterpret_cast<const float2*>(p0 + col);
                        float2 t1 = *reinterpret_cast<const float2*>(p1 + col);
                        e[mi * 2 + 0] += c[mi][ni][0] * t0.x + c[mi][ni][1] * t0.y;
                        e[mi * 2 + 1] += c[mi][ni][2] * t1.x + c[mi][ni][3] * t1.y;
                    }
                }
            }
        }
    }

    // reduce quads (lanes l%4 cover different col pairs of the same row)
    float v4[4];
#pragma unroll
    for (int mi = 0; mi < 2; ++mi)
#pragma unroll
        for (int rs = 0; rs < 2; ++rs) {
            float v = e[mi * 2 + rs];
            v += __shfl_xor_sync(0xffffffffu, v, 1);
            v += __shfl_xor_sync(0xffffffffu, v, 2);
            v4[mi * 2 + rs] = v;
        }

    // cross-warp combine: wn=0 stores its half, wn=1 adds and writes out
    __syncthreads();   // protect sE region (aliases nothing, but order vs loop)
    if (wn == 0 && (lane & 3) == 0) {
#pragma unroll
        for (int mi = 0; mi < 2; ++mi)
#pragma unroll
            for (int rs = 0; rs < 2; ++rs) {
                int m = wm * 32 + mi * 16 + (lane >> 2) + rs * 8;
                sE[m] = v4[mi * 2 + rs];
            }
    }
    __syncthreads();
    if (wn == 1 && (lane & 3) == 0) {
#pragma unroll
        for (int mi = 0; mi < 2; ++mi)
#pragma unroll
            for (int rs = 0; rs < 2; ++rs) {
                int m = wm * 32 + mi * 16 + (lane >> 2) + rs * 8;
                int sid = sSid[m];
                if (sid >= 0) out[sid] = v4[mi * 2 + rs] + sE[m];
            }
    }
}

// ---------------------------------------------------------------------------
// launch
// ---------------------------------------------------------------------------
extern "C" void kernel_launch(void* const* d_in, const int* in_sizes, int n_in,
                              void* d_out, int out_size) {
    const int*   rels       = (const int*)d_in[0];
    const int*   terms_L    = (const int*)d_in[1];
    const int*   terms_R    = (const int*)d_in[2];
    const float* term_table = (const float*)d_in[3];
    const float* rel_table  = (const float*)d_in[4];
    const float* assoc      = (const float*)d_in[5];
    float*       out        = (float*)d_out;

    cudaFuncSetAttribute(k_energy, cudaFuncAttributeMaxDynamicSharedMemorySize,
                         SMEM_REQ);

    k_buildB<<<dim3(NR, 25), 256>>>(rel_table, assoc);
    k_hist<<<NHB, 256>>>(rels);
    k_scan<<<1, 64>>>();
    k_scatter<<<NHB, 256>>>(rels);
    k_energy<<<dim3(MAX_TILES, NR), 256, SMEM_REQ>>>(terms_L, terms_R,
                                                     term_table, out);
}

// round 5
// speedup vs baseline: 3.0165x; 1.0710x over previous
#include <cuda_runtime.h>
#include <cuda_fp16.h>
#include <cstdint>

// ---------------------------------------------------------------------------
// Problem constants
// ---------------------------------------------------------------------------
#define NB  500000
#define D   300
#define NR  40
#define RD  5
#define NHB 128
#define CH  ((NB + NHB - 1) / NHB)
#define TILE_M    128
#define MAX_TILES 128
#define STRIDE_A  648          // fp16 elems per A row (640 data + 8 pad)
#define STRIDE_B  72           // fp16 per B chunk row (64 data + 8 pad, baked in gmem)
#define A_BYTES   (TILE_M * STRIDE_A * 2)      // 165888
#define CHUNK_HALFS (64 * STRIDE_B)            // 4608
#define CHUNK_BYTES (CHUNK_HALFS * 2)          // 9216
#define NCHUNKS   50           // per (r): nc(5) x [Bhi kc0..4, Blo kc0..4]
#define PDEPTH    4            // bulk-copy pipeline depth

// ---------------------------------------------------------------------------
// Device scratch
// ---------------------------------------------------------------------------
// Pre-chunked, pre-padded B operand stream:
// layout [r][nc][chunk(10: hi kc0..4, lo kc0..4)][64 n-rows][72 halfs]
__device__ __half g_Bpk[(size_t)NR * NCHUNKS * CHUNK_HALFS];   // 18.4 MB
__device__ int g_order[NB];
__device__ int g_offsets[NR + 1];
__device__ int g_blkhist[NHB * NR];
__device__ int g_blkbase[NHB * NR];

// ---------------------------------------------------------------------------
// Primitives (all sm_90-baseline or older; no tcgen05 / no "a"-features)
// ---------------------------------------------------------------------------
__device__ __forceinline__ uint32_t smem_u32(const void* p) {
    uint32_t a;
    asm("{ .reg .u64 t; cvta.to.shared.u64 t, %1; cvt.u32.u64 %0, t; }"
        : "=r"(a) : "l"(p));
    return a;
}
__device__ __forceinline__ void ldsm_x4(uint32_t r[4], uint32_t addr) {
    asm volatile("ldmatrix.sync.aligned.m8n8.x4.shared.b16 {%0,%1,%2,%3}, [%4];"
                 : "=r"(r[0]), "=r"(r[1]), "=r"(r[2]), "=r"(r[3]) : "r"(addr));
}
__device__ __forceinline__ void mma16816(float c[4], const uint32_t a[4],
                                         const uint32_t b0, const uint32_t b1) {
    asm volatile(
        "mma.sync.aligned.m16n8k16.row.col.f32.f16.f16.f32 "
        "{%0,%1,%2,%3}, {%4,%5,%6,%7}, {%8,%9}, {%0,%1,%2,%3};"
        : "+f"(c[0]), "+f"(c[1]), "+f"(c[2]), "+f"(c[3])
        : "r"(a[0]), "r"(a[1]), "r"(a[2]), "r"(a[3]), "r"(b0), "r"(b1));
}
// single-instruction bulk copy gmem->smem with mbarrier completion (sm_90)
__device__ __forceinline__ void bulk_g2s(uint32_t dst, const void* src,
                                         uint32_t bytes, uint32_t mbar) {
    asm volatile(
        "cp.async.bulk.shared::cluster.global.mbarrier::complete_tx::bytes "
        "[%0], [%1], %2, [%3];"
        :: "r"(dst), "l"(src), "r"(bytes), "r"(mbar) : "memory");
}
#define MBARRIER_INIT(mb, cnt) \
    asm volatile("mbarrier.init.shared.b64 [%0], %1;" \
                 :: "r"((uint32_t)(mb)), "r"((uint32_t)(cnt)) : "memory")
#define MBARRIER_EXPECT_TX(mb, n) \
    asm volatile("mbarrier.arrive.expect_tx.shared.b64 _, [%0], %1;" \
                 :: "r"((uint32_t)(mb)), "r"((uint32_t)(n)) : "memory")
#define MBARRIER_WAIT_PARITY(mb, ph) do {                                          \
    uint32_t _m = (uint32_t)(mb); uint32_t _p = (uint32_t)(ph); uint32_t _d;       \
    asm volatile("{\n\t.reg .pred p;\n\t"                                          \
        "mbarrier.try_wait.parity.acquire.cta.shared::cta.b64 p, [%1], %2;\n\t"    \
        "selp.b32 %0, 1, 0, p;\n\t}" : "=r"(_d) : "r"(_m), "r"(_p) : "memory");    \
    if (!_d) {                                                                     \
        asm volatile("{\n\t.reg .pred P1;\n\t"                                     \
            "WL_%=:\n\t"                                                           \
            "mbarrier.try_wait.parity.acquire.cta.shared::cta.b64 P1, [%0], %1, 0x989680;\n\t" \
            "@P1 bra.uni WD_%=;\n\t"                                               \
            "bra.uni WL_%=;\n\t"                                                   \
            "WD_%=:\n\t}" :: "r"(_m), "r"(_p) : "memory");                         \
    }                                                                              \
} while (0)

// ---------------------------------------------------------------------------
// Kernel 1: build pre-chunked B stream.
// chunk[r][nc][hi kc] and [lo kc]: B[n][k=j] = sum_i rel[r,i]*assoc[i][j][n]
// grid (NR, 25): y -> (jc=kc, nc); 64j x 64n tile per block.
// ---------------------------------------------------------------------------
__global__ void k_buildB(const float* __restrict__ rel_table,
                         const float* __restrict__ assoc) {
    __shared__ float sm[64][65];
    int r = blockIdx.x, jc = blockIdx.y / 5, nc = blockIdx.y % 5;
    float rv[RD];
#pragma unroll
    for (int i = 0; i < RD; ++i) rv[i] = rel_table[r * RD + i];
#pragma unroll
    for (int it = 0; it < 16; ++it) {
        int idx = threadIdx.x + it * 256;
        int jl = idx >> 6, nl = idx & 63;
        int j = jc * 64 + jl, n = nc * 64 + nl;
        float v = 0.f;
        if (j < D && n < D) {
#pragma unroll
            for (int i = 0; i < RD; ++i)
                v += rv[i] * assoc[((size_t)i * D + j) * D + n];
        }
        sm[jl][nl] = v;
    }
    __syncthreads();
    size_t hi_base = (((size_t)r * 5 + nc) * 10 + jc) * CHUNK_HALFS;
    size_t lo_base = (((size_t)r * 5 + nc) * 10 + 5 + jc) * CHUNK_HALFS;
#pragma unroll
    for (int it = 0; it < 16; ++it) {
        int idx = threadIdx.x + it * 256;
        int nl = idx >> 6, jl = idx & 63;
        float v = sm[jl][nl];
        __half hi = __float2half_rn(v);
        __half lo = __float2half_rn(v - __half2float(hi));
        g_Bpk[hi_base + nl * STRIDE_B + jl] = hi;
        g_Bpk[lo_base + nl * STRIDE_B + jl] = lo;
    }
}

// ---------------------------------------------------------------------------
// Kernels 2-4: counting sort by relation (verified R1/R4)
// ---------------------------------------------------------------------------
__global__ void k_hist(const int* __restrict__ rels) {
    __shared__ int h[NR];
    if (threadIdx.x < NR) h[threadIdx.x] = 0;
    __syncthreads();
    int start = blockIdx.x * CH, end = min(NB, start + CH);
    for (int i = start + threadIdx.x; i < end; i += blockDim.x)
        atomicAdd(&h[rels[i]], 1);
    __syncthreads();
    if (threadIdx.x < NR) g_blkhist[blockIdx.x * NR + threadIdx.x] = h[threadIdx.x];
}

__global__ void k_scan() {
    __shared__ int tot[NR];
    int r = threadIdx.x;
    if (r < NR) {
        int run = 0;
        for (int b = 0; b < NHB; b++) {
            g_blkbase[b * NR + r] = run;
            run += g_blkhist[b * NR + r];
        }
        tot[r] = run;
    }
    __syncthreads();
    if (threadIdx.x == 0) {
        int acc = 0;
        for (int rr = 0; rr < NR; rr++) { g_offsets[rr] = acc; acc += tot[rr]; }
        g_offsets[NR] = acc;
    }
    __syncthreads();
    if (r < NR) {
        int off = g_offsets[r];
        for (int b = 0; b < NHB; b++) g_blkbase[b * NR + r] += off;
    }
}

__global__ void k_scatter(const int* __restrict__ rels) {
    __shared__ int cur[NR];
    if (threadIdx.x < NR) cur[threadIdx.x] = g_blkbase[blockIdx.x * NR + threadIdx.x];
    __syncthreads();
    int start = blockIdx.x * CH, end = min(NB, start + CH);
    for (int i = start + threadIdx.x; i < end; i += blockDim.x) {
        int pos = atomicAdd(&cur[rels[i]], 1);
        g_order[pos] = i;
    }
}

// ---------------------------------------------------------------------------
// Kernel 5: HMMA energy, bulk-copy B pipeline.
//   smem: B ring [4][9216] | A [128][648] hi/lo | mbars | indices | sE
//   50 chunks/block: per nc, 5x Bhi (A_hi + A_lo passes, B frags reused),
//   then 5x Blo (A_hi pass). Epilogue per nc dots with tR from gmem.
// ---------------------------------------------------------------------------
#define SB_OFF    0
#define SA_OFF    (PDEPTH * CHUNK_BYTES)                 // 36864
#define MB_OFF    (SA_OFF + A_BYTES)                     // 202752
#define IDX_OFF   (MB_OFF + 32)
#define SMEM_REQ  (IDX_OFF + 3 * TILE_M * 4 + TILE_M * 4)  // 204832

extern __shared__ char smem_dyn[];

__global__ __launch_bounds__(256, 1)
void k_energy(const int* __restrict__ terms_L,
              const int* __restrict__ terms_R,
              const float* __restrict__ term_table,
              float* __restrict__ out) {
    int r = blockIdx.y;
    int tile = blockIdx.x;
    int lo_off = g_offsets[r];
    int cnt = g_offsets[r + 1] - lo_off;
    if (tile * TILE_M >= cnt) return;
    int base = lo_off + tile * TILE_M;
    int nvalid = min(TILE_M, cnt - tile * TILE_M);

    char* sA = smem_dyn + SA_OFF;
    int* sSid = (int*)(smem_dyn + IDX_OFF);
    int* sIL = sSid + TILE_M;
    int* sIR = sIL + TILE_M;
    float* sE = (float*)(sIR + TILE_M);
    uint32_t u_base = smem_u32(smem_dyn);
    uint32_t u_sB = u_base + SB_OFF;
    uint32_t u_sA = u_base + SA_OFF;
    uint32_t u_mb = u_base + MB_OFF;

    int tid = threadIdx.x;
    int lane = tid & 31;
    int wid = tid >> 5;
    int wm = wid & 3;
    int wn = wid >> 2;

    if (tid < TILE_M) {
        int sid = (tid < nvalid) ? g_order[base + tid] : -1;
        sSid[tid] = sid;
        sIL[tid] = (sid >= 0) ? terms_L[sid] : 0;
        sIR[tid] = (sid >= 0) ? terms_R[sid] : 0;
    }
    if (tid == 0) {
#pragma unroll
        for (int b = 0; b < PDEPTH; ++b) MBARRIER_INIT(u_mb + b * 8, 1);
    }
    __syncthreads();

    // prologue: kick off first PDEPTH chunk loads (single thread, 1 instr each)
    const __half* bsrc = g_Bpk + (size_t)r * NCHUNKS * CHUNK_HALFS;
    if (tid == 0) {
#pragma unroll
        for (int p = 0; p < PDEPTH; ++p) {
            MBARRIER_EXPECT_TX(u_mb + p * 8, CHUNK_BYTES);
            bulk_g2s(u_sB + p * CHUNK_BYTES, bsrc + (size_t)p * CHUNK_HALFS,
                     CHUNK_BYTES, u_mb + p * 8);
        }
    }

    // Build A: fp16 hi (cols 0..319) and lo (cols 320..639), zero-pad k>=300
#pragma unroll 4
    for (int idx = tid; idx < TILE_M * 160; idx += 256) {
        int m = idx / 160;
        int c2 = (idx % 160) * 2;
        float2 v = make_float2(0.f, 0.f);
        if (c2 < D)
            v = *reinterpret_cast<const float2*>(term_table + (size_t)sIL[m] * D + c2);
        __half hx = __float2half_rn(v.x), hy = __float2half_rn(v.y);
        __half lx = __float2half_rn(v.x - __half2float(hx));
        __half ly = __float2half_rn(v.y - __half2float(hy));
        *reinterpret_cast<__half2*>(sA + ((size_t)m * STRIDE_A + c2) * 2) =
            __halves2half2(hx, hy);
        *reinterpret_cast<__half2*>(sA + ((size_t)m * STRIDE_A + 320 + c2) * 2) =
            __halves2half2(lx, ly);
    }
    __syncthreads();   // A complete before any warp's MMA

    float c[2][4][4];
    float e[4] = {0.f, 0.f, 0.f, 0.f};

    for (int s = 0; s < NCHUNKS; ++s) {
        int b = s & (PDEPTH - 1);
        MBARRIER_WAIT_PARITY(u_mb + b * 8, (s >> 2) & 1);

        int nc = s / 10, t = s - nc * 10;
        int isHi = (t < 5);
        int kc = isHi ? t : t - 5;
        if (t == 0) {
#pragma unroll
            for (int mi = 0; mi < 2; ++mi)
#pragma unroll
                for (int ni = 0; ni < 4; ++ni)
#pragma unroll
                    for (int q = 0; q < 4; ++q) c[mi][ni][q] = 0.f;
        }
        uint32_t bbuf = u_sB + (uint32_t)b * CHUNK_BYTES;
        int ahi_base = kc * 64;

#pragma unroll
        for (int k16 = 0; k16 < 4; ++k16) {
            uint32_t bf[2][4];
#pragma unroll
            for (int g = 0; g < 2; ++g) {
                int brow = wn * 32 + g * 16 + ((lane >> 4) << 3) + (lane & 7);
                int bcol = k16 * 16 + ((lane >> 3) & 1) * 8;
                ldsm_x4(bf[g], bbuf + (brow * STRIDE_B + bcol) * 2);
            }
            uint32_t a[2][4];
#pragma unroll
            for (int mi = 0; mi < 2; ++mi) {
                int arow = wm * 32 + mi * 16 + (lane & 15);
                int acol = ahi_base + k16 * 16 + (lane >> 4) * 8;
                ldsm_x4(a[mi], u_sA + (arow * STRIDE_A + acol) * 2);
            }
#pragma unroll
            for (int mi = 0; mi < 2; ++mi)
#pragma unroll
                for (int ni = 0; ni < 4; ++ni)
                    mma16816(c[mi][ni], a[mi], bf[ni >> 1][(ni & 1) * 2],
                             bf[ni >> 1][(ni & 1) * 2 + 1]);
            if (isHi) {
                // second pass from same B frags: A_lo
                uint32_t al[2][4];
#pragma unroll
                for (int mi = 0; mi < 2; ++mi) {
                    int arow = wm * 32 + mi * 16 + (lane & 15);
                    int acol = 320 + ahi_base + k16 * 16 + (lane >> 4) * 8;
                    ldsm_x4(al[mi], u_sA + (arow * STRIDE_A + acol) * 2);
                }
#pragma unroll
                for (int mi = 0; mi < 2; ++mi)
#pragma unroll
                    for (int ni = 0; ni < 4; ++ni)
                        mma16816(c[mi][ni], al[mi], bf[ni >> 1][(ni & 1) * 2],
                                 bf[ni >> 1][(ni & 1) * 2 + 1]);
            }
        }

        if (t == 9) {
            // epilogue for n-chunk nc: e += W (.) tR
#pragma unroll
            for (int mi = 0; mi < 2; ++mi) {
                int row0 = wm * 32 + mi * 16 + (lane >> 2);
                int row1 = row0 + 8;
                const float* p0 = term_table + (size_t)sIR[row0] * D;
                const float* p1 = term_table + (size_t)sIR[row1] * D;
#pragma unroll
                for (int ni = 0; ni < 4; ++ni) {
                    int col = nc * 64 + wn * 32 + ni * 8 + 2 * (lane & 3);
                    if (col < D) {
                        float2 t0 = *reinterpret_cast<const float2*>(p0 + col);
                        float2 t1 = *reinterpret_cast<const float2*>(p1 + col);
                        e[mi * 2 + 0] += c[mi][ni][0] * t0.x + c[mi][ni][1] * t0.y;
                        e[mi * 2 + 1] += c[mi][ni][2] * t1.x + c[mi][ni][3] * t1.y;
                    }
                }
            }
        }

        __syncthreads();   // all warps done with buffer b before refill
        if (tid == 0 && s + PDEPTH < NCHUNKS) {
            MBARRIER_EXPECT_TX(u_mb + b * 8, CHUNK_BYTES);
            bulk_g2s(u_sB + b * CHUNK_BYTES,
                     bsrc + (size_t)(s + PDEPTH) * CHUNK_HALFS,
                     CHUNK_BYTES, u_mb + b * 8);
        }
    }

    // quad reduce (lanes l%4 cover different col pairs of the same row)
    float v4[4];
#pragma unroll
    for (int mi = 0; mi < 2; ++mi)
#pragma unroll
        for (int rs = 0; rs < 2; ++rs) {
            float v = e[mi * 2 + rs];
            v += __shfl_xor_sync(0xffffffffu, v, 1);
            v += __shfl_xor_sync(0xffffffffu, v, 2);
            v4[mi * 2 + rs] = v;
        }

    // cross-warp combine: wn=0 stores its half, wn=1 adds and writes out
    __syncthreads();
    if (wn == 0 && (lane & 3) == 0) {
#pragma unroll
        for (int mi = 0; mi < 2; ++mi)
#pragma unroll
            for (int rs = 0; rs < 2; ++rs) {
                int m = wm * 32 + mi * 16 + (lane >> 2) + rs * 8;
                sE[m] = v4[mi * 2 + rs];
            }
    }
    __syncthreads();
    if (wn == 1 && (lane & 3) == 0) {
#pragma unroll
        for (int mi = 0; mi < 2; ++mi)
#pragma unroll
            for (int rs = 0; rs < 2; ++rs) {
                int m = wm * 32 + mi * 16 + (lane >> 2) + rs * 8;
                int sid = sSid[m];
                if (sid >= 0) out[sid] = v4[mi * 2 + rs] + sE[m];
            }
    }
}

// ---------------------------------------------------------------------------
// launch
// ---------------------------------------------------------------------------
extern "C" void kernel_launch(void* const* d_in, const int* in_sizes, int n_in,
                              void* d_out, int out_size) {
    const int*   rels       = (const int*)d_in[0];
    const int*   terms_L    = (const int*)d_in[1];
    const int*   terms_R    = (const int*)d_in[2];
    const float* term_table = (const float*)d_in[3];
    const float* rel_table  = (const float*)d_in[4];
    const float* assoc      = (const float*)d_in[5];
    float*       out        = (float*)d_out;

    cudaFuncSetAttribute(k_energy, cudaFuncAttributeMaxDynamicSharedMemorySize,
                         SMEM_REQ);

    k_buildB<<<dim3(NR, 25), 256>>>(rel_table, assoc);
    k_hist<<<NHB, 256>>>(rels);
    k_scan<<<1, 64>>>();
    k_scatter<<<NHB, 256>>>(rels);
    k_energy<<<dim3(MAX_TILES, NR), 256, SMEM_REQ>>>(terms_L, terms_R,
                                                     term_table, out);
}

// round 7
// speedup vs baseline: 3.1220x; 1.0350x over previous
#include <cuda_runtime.h>
#include <cuda_fp16.h>
#include <cstdint>

// ---------------------------------------------------------------------------
// Problem constants
// ---------------------------------------------------------------------------
#define NB  500000
#define D   300
#define NR  40
#define RD  5
#define NHB 128
#define CH  ((NB + NHB - 1) / NHB)
#define TILE_M    128
#define MAX_TILES 128
#define STRIDE_A  648          // fp16 elems per A row (640 data + 8 pad)
#define STRIDE_B  72           // fp16 per B chunk row (64 data + 8 pad, baked in gmem)
#define A_BYTES   (TILE_M * STRIDE_A * 2)      // 165888
#define CHUNK_HALFS (64 * STRIDE_B)            // 4608
#define CHUNK_BYTES (CHUNK_HALFS * 2)          // 9216
#define NCHUNKS   50           // per r: nc(5) x [hi kc0..4, lo kc0..4]
#define PDEPTH    4            // bulk-copy ring depth

// ---------------------------------------------------------------------------
// Device scratch
// ---------------------------------------------------------------------------
// Pre-chunked, pre-padded fp16 B stream:
// [r][nc][chunk(10: hi kc0..4, lo kc0..4)][64 n-rows][72 halfs]   (18.4 MB)
__device__ __half g_Bpk[(size_t)NR * NCHUNKS * CHUNK_HALFS];
__device__ int g_order[NB];
__device__ int g_offsets[NR + 1];
__device__ int g_blkhist[NHB * NR];
__device__ int g_blkbase[NHB * NR];

// ---------------------------------------------------------------------------
// Primitives (sm_90-baseline or older; no tcgen05 / no "a"-features)
// ---------------------------------------------------------------------------
__device__ __forceinline__ uint32_t smem_u32(const void* p) {
    uint32_t a;
    asm("{ .reg .u64 t; cvta.to.shared.u64 t, %1; cvt.u32.u64 %0, t; }"
        : "=r"(a) : "l"(p));
    return a;
}
__device__ __forceinline__ void ldsm_x4(uint32_t r[4], uint32_t addr) {
    asm volatile("ldmatrix.sync.aligned.m8n8.x4.shared.b16 {%0,%1,%2,%3}, [%4];"
                 : "=r"(r[0]), "=r"(r[1]), "=r"(r[2]), "=r"(r[3]) : "r"(addr));
}
__device__ __forceinline__ void mma16816(float c[4], const uint32_t a[4],
                                         const uint32_t b0, const uint32_t b1) {
    asm volatile(
        "mma.sync.aligned.m16n8k16.row.col.f32.f16.f16.f32 "
        "{%0,%1,%2,%3}, {%4,%5,%6,%7}, {%8,%9}, {%0,%1,%2,%3};"
        : "+f"(c[0]), "+f"(c[1]), "+f"(c[2]), "+f"(c[3])
        : "r"(a[0]), "r"(a[1]), "r"(a[2]), "r"(a[3]), "r"(b0), "r"(b1));
}
__device__ __forceinline__ void bulk_g2s(uint32_t dst, const void* src,
                                         uint32_t bytes, uint32_t mbar) {
    asm volatile(
        "cp.async.bulk.shared::cluster.global.mbarrier::complete_tx::bytes "
        "[%0], [%1], %2, [%3];"
        :: "r"(dst), "l"(src), "r"(bytes), "r"(mbar) : "memory");
}
#define MBARRIER_INIT(mb, cnt) \
    asm volatile("mbarrier.init.shared.b64 [%0], %1;" \
                 :: "r"((uint32_t)(mb)), "r"((uint32_t)(cnt)) : "memory")
#define MBARRIER_EXPECT_TX(mb, n) \
    asm volatile("mbarrier.arrive.expect_tx.shared.b64 _, [%0], %1;" \
                 :: "r"((uint32_t)(mb)), "r"((uint32_t)(n)) : "memory")
#define MBARRIER_ARRIVE(mb) \
    asm volatile("mbarrier.arrive.shared.b64 _, [%0];" \
                 :: "r"((uint32_t)(mb)) : "memory")
#define MBARRIER_WAIT_PARITY(mb, ph) do {                                          \
    uint32_t _m = (uint32_t)(mb); uint32_t _p = (uint32_t)(ph); uint32_t _d;       \
    asm volatile("{\n\t.reg .pred p;\n\t"                                          \
        "mbarrier.try_wait.parity.acquire.cta.shared::cta.b64 p, [%1], %2;\n\t"    \
        "selp.b32 %0, 1, 0, p;\n\t}" : "=r"(_d) : "r"(_m), "r"(_p) : "memory");    \
    if (!_d) {                                                                     \
        asm volatile("{\n\t.reg .pred P1;\n\t"                                     \
            "WL_%=:\n\t"                                                           \
            "mbarrier.try_wait.parity.acquire.cta.shared::cta.b64 P1, [%0], %1, 0x989680;\n\t" \
            "@P1 bra.uni WD_%=;\n\t"                                               \
            "bra.uni WL_%=;\n\t"                                                   \
            "WD_%=:\n\t}" :: "r"(_m), "r"(_p) : "memory");                         \
    }                                                                              \
} while (0)

// ---------------------------------------------------------------------------
// Kernel 1: pre-chunked fp16 hi/lo B stream.
// B[n][k=j] = sum_i rel[r,i]*assoc[i][j][n]
// grid (NR, 25): y -> (kc, nc); 64j x 64n tile per block.
// ---------------------------------------------------------------------------
__global__ void k_buildB(const float* __restrict__ rel_table,
                         const float* __restrict__ assoc) {
    __shared__ float sm[64][65];
    int r = blockIdx.x, kc = blockIdx.y / 5, nc = blockIdx.y % 5;
    float rv[RD];
#pragma unroll
    for (int i = 0; i < RD; ++i) rv[i] = rel_table[r * RD + i];
#pragma unroll
    for (int it = 0; it < 16; ++it) {
        int idx = threadIdx.x + it * 256;
        int jl = idx >> 6, nl = idx & 63;
        int j = kc * 64 + jl, n = nc * 64 + nl;
        float v = 0.f;
        if (j < D && n < D) {
#pragma unroll
            for (int i = 0; i < RD; ++i)
                v += rv[i] * assoc[((size_t)i * D + j) * D + n];
        }
        sm[jl][nl] = v;
    }
    __syncthreads();
    size_t hi_base = (((size_t)r * 5 + nc) * 10 + kc) * CHUNK_HALFS;
    size_t lo_base = (((size_t)r * 5 + nc) * 10 + 5 + kc) * CHUNK_HALFS;
#pragma unroll
    for (int it = 0; it < 16; ++it) {
        int idx = threadIdx.x + it * 256;
        int nl = idx >> 6, jl = idx & 63;
        float v = sm[jl][nl];
        __half hi = __float2half_rn(v);
        __half lo = __float2half_rn(v - __half2float(hi));
        g_Bpk[hi_base + nl * STRIDE_B + jl] = hi;
        g_Bpk[lo_base + nl * STRIDE_B + jl] = lo;
    }
}

// ---------------------------------------------------------------------------
// Kernels 2-4: counting sort by relation (verified R1/R4/R5)
// ---------------------------------------------------------------------------
__global__ void k_hist(const int* __restrict__ rels) {
    __shared__ int h[NR];
    if (threadIdx.x < NR) h[threadIdx.x] = 0;
    __syncthreads();
    int start = blockIdx.x * CH, end = min(NB, start + CH);
    for (int i = start + threadIdx.x; i < end; i += blockDim.x)
        atomicAdd(&h[rels[i]], 1);
    __syncthreads();
    if (threadIdx.x < NR) g_blkhist[blockIdx.x * NR + threadIdx.x] = h[threadIdx.x];
}

__global__ void k_scan() {
    __shared__ int tot[NR];
    int r = threadIdx.x;
    if (r < NR) {
        int run = 0;
        for (int b = 0; b < NHB; b++) {
            g_blkbase[b * NR + r] = run;
            run += g_blkhist[b * NR + r];
        }
        tot[r] = run;
    }
    __syncthreads();
    if (threadIdx.x == 0) {
        int acc = 0;
        for (int rr = 0; rr < NR; rr++) { g_offsets[rr] = acc; acc += tot[rr]; }
        g_offsets[NR] = acc;
    }
    __syncthreads();
    if (r < NR) {
        int off = g_offsets[r];
        for (int b = 0; b < NHB; b++) g_blkbase[b * NR + r] += off;
    }
}

__global__ void k_scatter(const int* __restrict__ rels) {
    __shared__ int cur[NR];
    if (threadIdx.x < NR) cur[threadIdx.x] = g_blkbase[blockIdx.x * NR + threadIdx.x];
    __syncthreads();
    int start = blockIdx.x * CH, end = min(NB, start + CH);
    for (int i = start + threadIdx.x; i < end; i += blockDim.x) {
        int pos = atomicAdd(&cur[rels[i]], 1);
        g_order[pos] = i;
    }
}

// ---------------------------------------------------------------------------
// Kernel 5: HMMA energy, barrier-free producer-consumer ring,
// 3-term hi/lo numerics (measured rel_err 7.8e-6 in R5).
//   50 chunks: nc(5) x [hi kc(5): A_hi + A_lo passes | lo kc(5): A_hi pass]
//   full mbar (count1 + expect_tx) / empty mbar (count 8) per ring buffer.
//   NO __syncthreads in the mainloop.
// ---------------------------------------------------------------------------
#define SB_OFF    0
#define SA_OFF    (PDEPTH * CHUNK_BYTES)                 // 36864
#define MB_OFF    (SA_OFF + A_BYTES)                     // 202752 (full[4], empty[4])
#define IDX_OFF   (MB_OFF + 64)
#define SMEM_REQ  (IDX_OFF + 3 * TILE_M * 4 + TILE_M * 4)

extern __shared__ char smem_dyn[];

__global__ __launch_bounds__(256, 1)
void k_energy(const int* __restrict__ terms_L,
              const int* __restrict__ terms_R,
              const float* __restrict__ term_table,
              float* __restrict__ out) {
    int r = blockIdx.y;
    int tile = blockIdx.x;
    int lo_off = g_offsets[r];
    int cnt = g_offsets[r + 1] - lo_off;
    if (tile * TILE_M >= cnt) return;
    int base = lo_off + tile * TILE_M;
    int nvalid = min(TILE_M, cnt - tile * TILE_M);

    char* sA = smem_dyn + SA_OFF;
    int* sSid = (int*)(smem_dyn + IDX_OFF);
    int* sIL = sSid + TILE_M;
    int* sIR = sIL + TILE_M;
    float* sE = (float*)(sIR + TILE_M);
    uint32_t u_base = smem_u32(smem_dyn);
    uint32_t u_sB = u_base + SB_OFF;
    uint32_t u_sA = u_base + SA_OFF;
    uint32_t u_mbF = u_base + MB_OFF;        // full[0..3]
    uint32_t u_mbE = u_base + MB_OFF + 32;   // empty[0..3]

    int tid = threadIdx.x;
    int lane = tid & 31;
    int wid = tid >> 5;
    int wm = wid & 3;
    int wn = wid >> 2;

    if (tid < TILE_M) {
        int sid = (tid < nvalid) ? g_order[base + tid] : -1;
        sSid[tid] = sid;
        sIL[tid] = (sid >= 0) ? terms_L[sid] : 0;
        sIR[tid] = (sid >= 0) ? terms_R[sid] : 0;
    }
    if (tid == 0) {
#pragma unroll
        for (int b = 0; b < PDEPTH; ++b) {
            MBARRIER_INIT(u_mbF + b * 8, 1);
            MBARRIER_INIT(u_mbE + b * 8, 8);
        }
    }
    __syncthreads();

    // prologue: first PDEPTH chunk loads
    const __half* bsrc = g_Bpk + (size_t)r * NCHUNKS * CHUNK_HALFS;
    if (tid == 0) {
#pragma unroll
        for (int p = 0; p < PDEPTH; ++p) {
            MBARRIER_EXPECT_TX(u_mbF + p * 8, CHUNK_BYTES);
            bulk_g2s(u_sB + p * CHUNK_BYTES, bsrc + (size_t)p * CHUNK_HALFS,
                     CHUNK_BYTES, u_mbF + p * 8);
        }
    }

    // Build A: fp16 hi (cols 0..319) and lo (cols 320..639), zero-pad k>=300
#pragma unroll 4
    for (int idx = tid; idx < TILE_M * 160; idx += 256) {
        int m = idx / 160;
        int c2 = (idx % 160) * 2;
        float2 v = make_float2(0.f, 0.f);
        if (c2 < D)
            v = *reinterpret_cast<const float2*>(term_table + (size_t)sIL[m] * D + c2);
        __half hx = __float2half_rn(v.x), hy = __float2half_rn(v.y);
        __half lx = __float2half_rn(v.x - __half2float(hx));
        __half ly = __float2half_rn(v.y - __half2float(hy));
        *reinterpret_cast<__half2*>(sA + ((size_t)m * STRIDE_A + c2) * 2) =
            __halves2half2(hx, hy);
        *reinterpret_cast<__half2*>(sA + ((size_t)m * STRIDE_A + 320 + c2) * 2) =
            __halves2half2(lx, ly);
    }
    __syncthreads();   // A + indices complete before any warp's MMA

    float c[2][4][4];
    float e[4] = {0.f, 0.f, 0.f, 0.f};

    for (int s = 0; s < NCHUNKS; ++s) {
        // producer (thread 0): refill buffer of chunk s-1 with chunk s-1+PDEPTH
        if (tid == 0 && s >= 1 && (s - 1) + PDEPTH < NCHUNKS) {
            int cprev = s - 1;
            int b2 = cprev & (PDEPTH - 1);
            MBARRIER_WAIT_PARITY(u_mbE + b2 * 8, (cprev >> 2) & 1);
            MBARRIER_EXPECT_TX(u_mbF + b2 * 8, CHUNK_BYTES);
            bulk_g2s(u_sB + b2 * CHUNK_BYTES,
                     bsrc + (size_t)(cprev + PDEPTH) * CHUNK_HALFS,
                     CHUNK_BYTES, u_mbF + b2 * 8);
        }

        int b = s & (PDEPTH - 1);
        MBARRIER_WAIT_PARITY(u_mbF + b * 8, (s >> 2) & 1);

        int nc = s / 10, t = s - nc * 10;
        int isHi = (t < 5);
        int kc = isHi ? t : t - 5;
        if (t == 0) {
#pragma unroll
            for (int mi = 0; mi < 2; ++mi)
#pragma unroll
                for (int ni = 0; ni < 4; ++ni)
#pragma unroll
                    for (int q = 0; q < 4; ++q) c[mi][ni][q] = 0.f;
        }
        uint32_t bbuf = u_sB + (uint32_t)b * CHUNK_BYTES;
        int abase = kc * 64;

#pragma unroll
        for (int k16 = 0; k16 < 4; ++k16) {
            uint32_t bf[2][4];
#pragma unroll
            for (int g = 0; g < 2; ++g) {
                int brow = wn * 32 + g * 16 + ((lane >> 4) << 3) + (lane & 7);
                int bcol = k16 * 16 + ((lane >> 3) & 1) * 8;
                ldsm_x4(bf[g], bbuf + (brow * STRIDE_B + bcol) * 2);
            }
            uint32_t a[2][4];
#pragma unroll
            for (int mi = 0; mi < 2; ++mi) {
                int arow = wm * 32 + mi * 16 + (lane & 15);
                int acol = abase + k16 * 16 + (lane >> 4) * 8;
                ldsm_x4(a[mi], u_sA + (arow * STRIDE_A + acol) * 2);
            }
#pragma unroll
            for (int mi = 0; mi < 2; ++mi)
#pragma unroll
                for (int ni = 0; ni < 4; ++ni)
                    mma16816(c[mi][ni], a[mi], bf[ni >> 1][(ni & 1) * 2],
                             bf[ni >> 1][(ni & 1) * 2 + 1]);
            if (isHi) {
                // A_lo pass, same B fragments (cross term 1; cross term 2 is
                // the lo-B chunks with A_hi)
                uint32_t al[2][4];
#pragma unroll
                for (int mi = 0; mi < 2; ++mi) {
                    int arow = wm * 32 + mi * 16 + (lane & 15);
                    int acol = 320 + abase + k16 * 16 + (lane >> 4) * 8;
                    ldsm_x4(al[mi], u_sA + (arow * STRIDE_A + acol) * 2);
                }
#pragma unroll
                for (int mi = 0; mi < 2; ++mi)
#pragma unroll
                    for (int ni = 0; ni < 4; ++ni)
                        mma16816(c[mi][ni], al[mi], bf[ni >> 1][(ni & 1) * 2],
                                 bf[ni >> 1][(ni & 1) * 2 + 1]);
            }
        }

        // this warp is done with buffer b
        if (lane == 0) MBARRIER_ARRIVE(u_mbE + b * 8);

        if (t == 9) {
            // epilogue for n-chunk nc: e += W (.) tR
#pragma unroll
            for (int mi = 0; mi < 2; ++mi) {
                int row0 = wm * 32 + mi * 16 + (lane >> 2);
                int row1 = row0 + 8;
                const float* p0 = term_table + (size_t)sIR[row0] * D;
                const float* p1 = term_table + (size_t)sIR[row1] * D;
#pragma unroll
                for (int ni = 0; ni < 4; ++ni) {
                    int col = nc * 64 + wn * 32 + ni * 8 + 2 * (lane & 3);
                    if (col < D) {
                        float2 t0 = *reinterpret_cast<const float2*>(p0 + col);
                        float2 t1 = *reinterpret_cast<const float2*>(p1 + col);
                        e[mi * 2 + 0] += c[mi][ni][0] * t0.x + c[mi][ni][1] * t0.y;
                        e[mi * 2 + 1] += c[mi][ni][2] * t1.x + c[mi][ni][3] * t1.y;
                    }
                }
            }
        }
    }

    // quad reduce (lanes l%4 cover different col pairs of the same row)
    float v4[4];
#pragma unroll
    for (int mi = 0; mi < 2; ++mi)
#pragma unroll
        for (int rs = 0; rs < 2; ++rs) {
            float v = e[mi * 2 + rs];
            v += __shfl_xor_sync(0xffffffffu, v, 1);
            v += __shfl_xor_sync(0xffffffffu, v, 2);
            v4[mi * 2 + rs] = v;
        }

    // cross-warp combine: wn=0 stores its half, wn=1 adds and writes out
    __syncthreads();
    if (wn == 0 && (lane & 3) == 0) {
#pragma unroll
        for (int mi = 0; mi < 2; ++mi)
#pragma unroll
            for (int rs = 0; rs < 2; ++rs) {
                int m = wm * 32 + mi * 16 + (lane >> 2) + rs * 8;
                sE[m] = v4[mi * 2 + rs];
            }
    }
    __syncthreads();
    if (wn == 1 && (lane & 3) == 0) {
#pragma unroll
        for (int mi = 0; mi < 2; ++mi)
#pragma unroll
            for (int rs = 0; rs < 2; ++rs) {
                int m = wm * 32 + mi * 16 + (lane >> 2) + rs * 8;
                int sid = sSid[m];
                if (sid >= 0) out[sid] = v4[mi * 2 + rs] + sE[m];
            }
    }
}

// ---------------------------------------------------------------------------
// launch
// ---------------------------------------------------------------------------
extern "C" void kernel_launch(void* const* d_in, const int* in_sizes, int n_in,
                              void* d_out, int out_size) {
    const int*   rels       = (const int*)d_in[0];
    const int*   terms_L    = (const int*)d_in[1];
    const int*   terms_R    = (const int*)d_in[2];
    const float* term_table = (const float*)d_in[3];
    const float* rel_table  = (const float*)d_in[4];
    const float* assoc      = (const float*)d_in[5];
    float*       out        = (float*)d_out;

    cudaFuncSetAttribute(k_energy, cudaFuncAttributeMaxDynamicSharedMemorySize,
                         SMEM_REQ);

    k_buildB<<<dim3(NR, 25), 256>>>(rel_table, assoc);
    k_hist<<<NHB, 256>>>(rels);
    k_scan<<<1, 64>>>();
    k_scatter<<<NHB, 256>>>(rels);
    k_energy<<<dim3(MAX_TILES, NR), 256, SMEM_REQ>>>(terms_L, terms_R,
                                                     term_table, out);
}